// round 1
// baseline (speedup 1.0000x reference)
#include <cuda_runtime.h>

#define NN 50000
#define MM 800000
#define HH 64
#define EE 8
#define INN 16
#define DIN 137  // 1 + 2*H + E
#define LL 2

// ---------------- device scratch (no allocs allowed) ----------------
__device__ float g_h0[NN * HH];
__device__ float g_h1[NN * HH];
__device__ float g_x[NN * 3];
__device__ float g_aggmsg[NN * HH];
__device__ float g_aggf[NN * 3];
__device__ float g_cnt[NN];

__device__ __forceinline__ float silu_f(float v) {
    return v / (1.0f + __expf(-v));
}

// acc[0..63] += s * w[0..63]   (w: shared, broadcast, vectorized LDS.128)
__device__ __forceinline__ void fma_row(float* acc, float s, const float* w) {
    const float4* w4 = (const float4*)w;
#pragma unroll
    for (int j4 = 0; j4 < HH / 4; j4++) {
        float4 t = w4[j4];
        acc[j4 * 4 + 0] += s * t.x;
        acc[j4 * 4 + 1] += s * t.y;
        acc[j4 * 4 + 2] += s * t.z;
        acc[j4 * 4 + 3] += s * t.w;
    }
}

// ---------------- embedding: h0 = h @ embW + embB ----------------
__global__ void k_embed(const float* __restrict__ h_in,
                        const float* __restrict__ W,
                        const float* __restrict__ b) {
    __shared__ float sW[INN * HH];
    __shared__ float sb[HH];
    for (int i = threadIdx.x; i < INN * HH; i += blockDim.x) sW[i] = W[i];
    for (int i = threadIdx.x; i < HH; i += blockDim.x) sb[i] = b[i];
    __syncthreads();
    int n = blockIdx.x * blockDim.x + threadIdx.x;
    if (n >= NN) return;
    float in[INN];
#pragma unroll
    for (int k = 0; k < INN; k++) in[k] = h_in[n * INN + k];
    float acc[HH];
#pragma unroll
    for (int j = 0; j < HH; j++) acc[j] = sb[j];
#pragma unroll
    for (int k = 0; k < INN; k++) fma_row(acc, in[k], &sW[k * HH]);
#pragma unroll
    for (int j = 0; j < HH; j++) g_h0[(size_t)n * HH + j] = acc[j];
}

// ---------------- degree count ----------------
__global__ void k_cnt(const int* __restrict__ row) {
    int e = blockIdx.x * blockDim.x + threadIdx.x;
    if (e < MM) atomicAdd(&g_cnt[row[e]], 1.0f);
}

// ---------------- fused edge kernel ----------------
// smem: W1[137*64] | W2T[64*64] | CW1[64*64] | B1 | B2 | CB1 | CW2 | CB2(1)
#define EDGE_SMEM_FLOATS (DIN * HH + HH * HH + HH * HH + 4 * HH + 1)

__global__ __launch_bounds__(128, 2) void k_edge(
    const float* __restrict__ h_in,
    const int* __restrict__ row, const int* __restrict__ col,
    const float* __restrict__ efea,
    const float* __restrict__ W1, const float* __restrict__ B1,
    const float* __restrict__ W2, const float* __restrict__ B2,
    const float* __restrict__ CW1, const float* __restrict__ CB1,
    const float* __restrict__ CW2, const float* __restrict__ CB2) {
    extern __shared__ float sm[];
    float* sW1  = sm;                       // DIN*HH
    float* sW2T = sW1 + DIN * HH;           // HH*HH, [j][k]
    float* sCW1 = sW2T + HH * HH;           // HH*HH, [k][j]
    float* sB1  = sCW1 + HH * HH;
    float* sB2  = sB1 + HH;
    float* sCB1 = sB2 + HH;
    float* sCW2 = sCB1 + HH;
    float* sCB2 = sCW2 + HH;

    const int tid = threadIdx.x, bs = blockDim.x;
    for (int i = tid; i < DIN * HH; i += bs) sW1[i] = W1[i];
    for (int i = tid; i < HH * HH; i += bs) {
        int k = i >> 6, j = i & 63;
        sW2T[j * HH + k] = W2[i];  // transpose: output-major
    }
    for (int i = tid; i < HH * HH; i += bs) sCW1[i] = CW1[i];
    for (int i = tid; i < HH; i += bs) {
        sB1[i] = B1[i]; sB2[i] = B2[i]; sCB1[i] = CB1[i]; sCW2[i] = CW2[i];
    }
    if (tid == 0) sCB2[0] = CB2[0];
    __syncthreads();

    int e = blockIdx.x * bs + tid;
    if (e >= MM) return;

    const int r = row[e], c = col[e];
    const float rx = g_x[r * 3 + 0] - g_x[c * 3 + 0];
    const float ry = g_x[r * 3 + 1] - g_x[c * 3 + 1];
    const float rz = g_x[r * 3 + 2] - g_x[c * 3 + 2];
    const float r2 = rx * rx + ry * ry + rz * rz;

    // hidden1 = silu(s @ W1 + b1), s = [r2, h[r], h[c], efea]
    float hid[HH];
#pragma unroll
    for (int j = 0; j < HH; j++) hid[j] = sB1[j];
    fma_row(hid, r2, &sW1[0]);
    {
        const float4* hr = (const float4*)&h_in[(size_t)r * HH];
#pragma unroll
        for (int q = 0; q < HH / 4; q++) {
            float4 v = hr[q];
            fma_row(hid, v.x, &sW1[(1 + q * 4 + 0) * HH]);
            fma_row(hid, v.y, &sW1[(1 + q * 4 + 1) * HH]);
            fma_row(hid, v.z, &sW1[(1 + q * 4 + 2) * HH]);
            fma_row(hid, v.w, &sW1[(1 + q * 4 + 3) * HH]);
        }
        const float4* hc = (const float4*)&h_in[(size_t)c * HH];
#pragma unroll
        for (int q = 0; q < HH / 4; q++) {
            float4 v = hc[q];
            fma_row(hid, v.x, &sW1[(1 + HH + q * 4 + 0) * HH]);
            fma_row(hid, v.y, &sW1[(1 + HH + q * 4 + 1) * HH]);
            fma_row(hid, v.z, &sW1[(1 + HH + q * 4 + 2) * HH]);
            fma_row(hid, v.w, &sW1[(1 + HH + q * 4 + 3) * HH]);
        }
        const float4* ef = (const float4*)&efea[(size_t)e * EE];
#pragma unroll
        for (int q = 0; q < EE / 4; q++) {
            float4 v = ef[q];
            fma_row(hid, v.x, &sW1[(1 + 2 * HH + q * 4 + 0) * HH]);
            fma_row(hid, v.y, &sW1[(1 + 2 * HH + q * 4 + 1) * HH]);
            fma_row(hid, v.z, &sW1[(1 + 2 * HH + q * 4 + 2) * HH]);
            fma_row(hid, v.w, &sW1[(1 + 2 * HH + q * 4 + 3) * HH]);
        }
    }
#pragma unroll
    for (int j = 0; j < HH; j++) hid[j] = silu_f(hid[j]);

    // msg = silu(hid @ W2 + b2), streamed in chunks of 16;
    // simultaneously: ch += msg_chunk @ CW1 rows, and atomic agg of msg.
    float ch[HH];
#pragma unroll
    for (int j = 0; j < HH; j++) ch[j] = sCB1[j];

    float* dst_msg = &g_aggmsg[(size_t)r * HH];
#pragma unroll
    for (int m0 = 0; m0 < HH; m0 += 16) {
        float mt[16];
#pragma unroll
        for (int jj = 0; jj < 16; jj++) {
            const int j = m0 + jj;
            float a = sB2[j];
            const float4* w4 = (const float4*)&sW2T[j * HH];
#pragma unroll
            for (int k4 = 0; k4 < HH / 4; k4++) {
                float4 t = w4[k4];
                a += hid[k4 * 4 + 0] * t.x + hid[k4 * 4 + 1] * t.y +
                     hid[k4 * 4 + 2] * t.z + hid[k4 * 4 + 3] * t.w;
            }
            mt[jj] = silu_f(a);
        }
#pragma unroll
        for (int jj = 0; jj < 16; jj++) atomicAdd(dst_msg + m0 + jj, mt[jj]);
#pragma unroll
        for (int kk = 0; kk < 16; kk++) fma_row(ch, mt[kk], &sCW1[(m0 + kk) * HH]);
    }

    // cm = silu(ch) @ CW2 + cb2
    float cm = sCB2[0];
#pragma unroll
    for (int k = 0; k < HH; k++) cm += silu_f(ch[k]) * sCW2[k];

    atomicAdd(&g_aggf[r * 3 + 0], rx * cm);
    atomicAdd(&g_aggf[r * 3 + 1], ry * cm);
    atomicAdd(&g_aggf[r * 3 + 2], rz * cm);
}

// ---------------- node kernel: coord update + node MLP ----------------
#define NODE_SMEM_FLOATS (2 * HH * HH + HH * HH + 2 * HH)

__global__ __launch_bounds__(128) void k_node(
    const float* __restrict__ h_in, float* __restrict__ h_out,
    const float* __restrict__ NW1, const float* __restrict__ NB1,
    const float* __restrict__ NW2, const float* __restrict__ NB2,
    float* __restrict__ out_x, float* __restrict__ out_h, int writeOut) {
    extern __shared__ float sm[];
    float* sW1  = sm;                    // [2H][H], k-major
    float* sW2T = sW1 + 2 * HH * HH;     // [j][k] transposed
    float* sB1  = sW2T + HH * HH;
    float* sB2  = sB1 + HH;

    const int tid = threadIdx.x, bs = blockDim.x;
    for (int i = tid; i < 2 * HH * HH; i += bs) sW1[i] = NW1[i];
    for (int i = tid; i < HH * HH; i += bs) {
        int k = i >> 6, j = i & 63;
        sW2T[j * HH + k] = NW2[i];
    }
    for (int i = tid; i < HH; i += bs) { sB1[i] = NB1[i]; sB2[i] = NB2[i]; }
    __syncthreads();

    int n = blockIdx.x * bs + tid;
    if (n >= NN) return;

    float hid[HH];
#pragma unroll
    for (int j = 0; j < HH; j++) hid[j] = sB1[j];
    {
        const float4* hv = (const float4*)&h_in[(size_t)n * HH];
#pragma unroll
        for (int q = 0; q < HH / 4; q++) {
            float4 v = hv[q];
            fma_row(hid, v.x, &sW1[(q * 4 + 0) * HH]);
            fma_row(hid, v.y, &sW1[(q * 4 + 1) * HH]);
            fma_row(hid, v.z, &sW1[(q * 4 + 2) * HH]);
            fma_row(hid, v.w, &sW1[(q * 4 + 3) * HH]);
        }
        const float4* mv = (const float4*)&g_aggmsg[(size_t)n * HH];
#pragma unroll
        for (int q = 0; q < HH / 4; q++) {
            float4 v = mv[q];
            fma_row(hid, v.x, &sW1[(HH + q * 4 + 0) * HH]);
            fma_row(hid, v.y, &sW1[(HH + q * 4 + 1) * HH]);
            fma_row(hid, v.z, &sW1[(HH + q * 4 + 2) * HH]);
            fma_row(hid, v.w, &sW1[(HH + q * 4 + 3) * HH]);
        }
    }
#pragma unroll
    for (int j = 0; j < HH; j++) hid[j] = silu_f(hid[j]);

#pragma unroll
    for (int j = 0; j < HH; j++) {
        float a = sB2[j];
        const float4* w4 = (const float4*)&sW2T[j * HH];
#pragma unroll
        for (int k4 = 0; k4 < HH / 4; k4++) {
            float4 t = w4[k4];
            a += hid[k4 * 4 + 0] * t.x + hid[k4 * 4 + 1] * t.y +
                 hid[k4 * 4 + 2] * t.z + hid[k4 * 4 + 3] * t.w;
        }
        h_out[(size_t)n * HH + j] = a;
        if (writeOut) out_h[(size_t)n * HH + j] = a;
    }

    // coord update: x += clip(sum_f / max(cnt,1), -100, 100)
    float cnt = g_cnt[n];
    float inv = 1.0f / fmaxf(cnt, 1.0f);
#pragma unroll
    for (int d = 0; d < 3; d++) {
        float tot = g_aggf[n * 3 + d] * inv;
        tot = fminf(fmaxf(tot, -100.0f), 100.0f);
        float nx = g_x[n * 3 + d] + tot;
        g_x[n * 3 + d] = nx;
        if (writeOut) out_x[n * 3 + d] = nx;
    }
}

// ---------------- launch ----------------
extern "C" void kernel_launch(void* const* d_in, const int* in_sizes, int n_in,
                              void* d_out, int out_size) {
    const float* x    = (const float*)d_in[0];
    const float* h    = (const float*)d_in[1];
    const int*   row  = (const int*)d_in[2];
    const int*   col  = (const int*)d_in[3];
    const float* efea = (const float*)d_in[4];
    const float* embW = (const float*)d_in[5];
    const float* embB = (const float*)d_in[6];
    const float* eW1  = (const float*)d_in[7];
    const float* eB1  = (const float*)d_in[8];
    const float* eW2  = (const float*)d_in[9];
    const float* eB2  = (const float*)d_in[10];
    const float* cW1  = (const float*)d_in[11];
    const float* cB1  = (const float*)d_in[12];
    const float* cW2  = (const float*)d_in[13];
    const float* cB2  = (const float*)d_in[14];
    const float* nW1  = (const float*)d_in[15];
    const float* nB1  = (const float*)d_in[16];
    const float* nW2  = (const float*)d_in[17];
    const float* nB2  = (const float*)d_in[18];
    float* out = (float*)d_out;

    void *p_x, *p_h0, *p_h1, *p_am, *p_af, *p_cnt;
    cudaGetSymbolAddress(&p_x, g_x);
    cudaGetSymbolAddress(&p_h0, g_h0);
    cudaGetSymbolAddress(&p_h1, g_h1);
    cudaGetSymbolAddress(&p_am, g_aggmsg);
    cudaGetSymbolAddress(&p_af, g_aggf);
    cudaGetSymbolAddress(&p_cnt, g_cnt);

    const int edge_smem = EDGE_SMEM_FLOATS * sizeof(float);
    const int node_smem = NODE_SMEM_FLOATS * sizeof(float);
    cudaFuncSetAttribute(k_edge, cudaFuncAttributeMaxDynamicSharedMemorySize, edge_smem);
    cudaFuncSetAttribute(k_node, cudaFuncAttributeMaxDynamicSharedMemorySize, node_smem);

    cudaMemcpyAsync(p_x, x, NN * 3 * sizeof(float), cudaMemcpyDeviceToDevice, 0);
    cudaMemsetAsync(p_cnt, 0, NN * sizeof(float), 0);
    k_cnt<<<(MM + 255) / 256, 256>>>(row);
    k_embed<<<(NN + 127) / 128, 128>>>(h, embW, embB);

    float* hbuf[2] = {(float*)p_h0, (float*)p_h1};
    float* out_x = out;
    float* out_h = out + (size_t)NN * 3;

    for (int i = 0; i < LL; i++) {
        cudaMemsetAsync(p_am, 0, (size_t)NN * HH * sizeof(float), 0);
        cudaMemsetAsync(p_af, 0, (size_t)NN * 3 * sizeof(float), 0);
        k_edge<<<(MM + 127) / 128, 128, edge_smem>>>(
            hbuf[i & 1], row, col, efea,
            eW1 + (size_t)i * DIN * HH, eB1 + (size_t)i * HH,
            eW2 + (size_t)i * HH * HH,  eB2 + (size_t)i * HH,
            cW1 + (size_t)i * HH * HH,  cB1 + (size_t)i * HH,
            cW2 + (size_t)i * HH,       cB2 + (size_t)i * 1);
        k_node<<<(NN + 127) / 128, 128, node_smem>>>(
            hbuf[i & 1], hbuf[(i + 1) & 1],
            nW1 + (size_t)i * 2 * HH * HH, nB1 + (size_t)i * HH,
            nW2 + (size_t)i * HH * HH,     nB2 + (size_t)i * HH,
            out_x, out_h, (i == LL - 1) ? 1 : 0);
    }
    (void)in_sizes; (void)n_in; (void)out_size;
}